// round 10
// baseline (speedup 1.0000x reference)
#include <cuda_runtime.h>

#define NB   2
#define NK   8
#define VOX  512000
#define B1   128
#define CHUNK 4000

typedef unsigned long long u64;

// ---------------- packed f32x2 helpers ----------------
__device__ __forceinline__ u64 pack2(float lo, float hi) {
    u64 r; asm("mov.b64 %0,{%1,%2};" : "=l"(r) : "f"(lo), "f"(hi)); return r;
}
__device__ __forceinline__ float2 unpack2(u64 p) {
    float2 f; asm("mov.b64 {%0,%1},%2;" : "=f"(f.x), "=f"(f.y) : "l"(p)); return f;
}
__device__ __forceinline__ void fma2(u64 &a, u64 v, u64 c) {
    asm("fma.rn.f32x2 %0,%1,%2,%0;" : "+l"(a) : "l"(v), "l"(c));
}

// 11-tap unnormalized Gaussian, sigma=4: g[t] = exp(-(t-5)^2/32), symmetric
__device__ __forceinline__ void mk_taps(u64* t) {
    const float g[6] = { 0.45783335f, 0.60653066f, 0.75483960f,
                         0.88249690f, 0.96923321f, 1.00000000f };
    #pragma unroll
    for (int i = 0; i < 6; i++) t[i] = pack2(g[i], g[i]);
}

// Sliding-window 11-tap conv, L outputs, L+10 inputs, ring of 11 accumulators.
template<int L, typename LoadF, typename EmitF>
__device__ __forceinline__ void slide11(const u64* taps, LoadF&& load, EmitF&& emit) {
    u64 acc[11];
    #pragma unroll
    for (int s = 0; s < 11; s++) acc[s] = 0ull;
    #pragma unroll
    for (int i = 0; i < L + 10; i++) {
        u64 v = load(i);
        #pragma unroll
        for (int j = 0; j <= 10; j++) {
            int o = i - 10 + j;
            if (o >= 0 && o < L) {
                int t = 10 - j;
                int u = (t <= 5) ? t : 10 - t;
                fma2(acc[o % 11], v, taps[u]);
            }
        }
        if (i >= 10) {
            emit(i - 10, acc[(i - 10) % 11]);
            acc[(i - 10) % 11] = 0ull;
        }
    }
}

// ---------------- scratch ----------------
__device__ float  g_part1[NB * B1 * 8];
__device__ float  g_mean[NK];
__device__ u64    g_bufA[NK * VOX];     // (w,pw) f32-packed, layout [nk][h][w][d]
__device__ float2 g_partC[NK * 80];     // per (nk,w) partial (num,den)

// ---------------- K1: partial sums for class means (float4 streams) ----------------
__global__ __launch_bounds__(256) void k_sums(const float* __restrict__ labels,
                                              const float* __restrict__ inputs) {
    int n = blockIdx.y, b = blockIdx.x;
    int j0 = b * (CHUNK / 4);                 // 1000 float4 per block
    float a[8];
    #pragma unroll
    for (int j = 0; j < 8; j++) a[j] = 0.f;
    const float4* ip4 = (const float4*)(inputs + (size_t)n * VOX);
    for (int j = j0 + threadIdx.x; j < j0 + CHUNK / 4; j += blockDim.x) {
        float4 iv = __ldg(ip4 + j);
        #pragma unroll
        for (int k = 0; k < 4; k++) {
            const float4* lp4 = (const float4*)(labels + (size_t)(n * 4 + k) * VOX);
            float4 lv = __ldg(lp4 + j);
            a[k]     += (lv.x + lv.y) + (lv.z + lv.w);
            a[4 + k] += (iv.x * lv.x + iv.y * lv.y) + (iv.z * lv.z + iv.w * lv.w);
        }
    }
    #pragma unroll
    for (int o = 16; o > 0; o >>= 1)
        #pragma unroll
        for (int j = 0; j < 8; j++)
            a[j] += __shfl_down_sync(0xffffffffu, a[j], o);
    __shared__ float s[8][8];
    int wid = threadIdx.x >> 5, lid = threadIdx.x & 31;
    if (lid == 0)
        #pragma unroll
        for (int j = 0; j < 8; j++) s[wid][j] = a[j];
    __syncthreads();
    if (threadIdx.x < 8) {
        int j = threadIdx.x;
        float acc = 0.f;
        #pragma unroll
        for (int w = 0; w < 8; w++) acc += s[w][j];
        g_part1[(size_t)(n * B1 + b) * 8 + j] = acc;
    }
}

// ---------------- K2: finish means ----------------
__global__ __launch_bounds__(256) void k_means() {
    int wid = threadIdx.x >> 5, lid = threadIdx.x & 31;   // wid = nk
    int n = wid >> 2, k = wid & 3;
    float sp = 0.f, sip = 0.f;
    for (int b = lid; b < B1; b += 32) {
        const float* p = g_part1 + (size_t)(n * B1 + b) * 8;
        sp  += p[k];
        sip += p[4 + k];
    }
    #pragma unroll
    for (int o = 16; o > 0; o >>= 1) {
        sp  += __shfl_down_sync(0xffffffffu, sp, o);
        sip += __shfl_down_sync(0xffffffffu, sip, o);
    }
    if (lid == 0) g_mean[wid] = sip / (sp + 5.12f);   // 1e-5 * 512000
}

// ---------------- KA: exp weights + conv along W (R4-exact) ----------------
// grid = NK*80 (nk,h); 240 active threads = 80 d-lanes x 3 w-segments
__global__ __launch_bounds__(256) void kA(const float* __restrict__ labels,
                                          const float* __restrict__ inputs) {
    int bx = blockIdx.x;
    int nk = bx / 80, h = bx % 80, n = nk >> 2;
    float m = g_mean[nk];
    int tid = threadIdx.x;
    if (tid >= 240) return;
    int d = tid % 80, seg = tid / 80;
    u64 taps[6]; mk_taps(taps);
    const float* ip = inputs + (size_t)n  * VOX + (size_t)h * 6400 + d;
    const float* lp = labels + (size_t)nk * VOX + (size_t)h * 6400 + d;
    u64*         op = g_bufA + (size_t)nk * VOX + (size_t)h * 6400 + d;
    int w0 = seg * 27;
    auto load = [&](int i) -> u64 {
        int w = w0 - 5 + i;
        if (w < 0 || w >= 80) return 0ull;
        float iv = __ldg(ip + w * 80);
        float lv = __ldg(lp + w * 80);
        float t  = iv - m;
        float q  = t * t; q = q * q;
        float wv = __expf(-q);
        return pack2(wv, lv * wv);
    };
    auto emit = [&](int o, u64 a) { op[(w0 + o) * 80] = a; };
    if (seg < 2) slide11<27>(taps, load, emit);
    else         slide11<26>(taps, load, emit);
}

// ---------------- KB: conv-H + conv-D + fused label reduce ----------------
// grid = NK*80, block = (nk,w). 4 subtiles: 2 d-chunks x 2 h-halves.
// Per subtile: cooperatively stage the raw bufA slab into smem (coalesced),
// conv-H from smem -> spk, conv-D over spk + label reduce. All conv work on smem.
__global__ __launch_bounds__(256) void kB(const float* __restrict__ labels) {
    int bx = blockIdx.x;
    int nk = bx / 80, w = bx % 80;
    int tid = threadIdx.x;

    __shared__ u64   raw[50 * 45];    // input slab: 50 h-rows x 45 d-cols
    __shared__ u64   spk[40 * 51];    // conv-H result, 40 h-rows x 50 d-cols (stride 51)
    __shared__ float slab[40 * 41];   // labels, 40 h-rows x 40 d-cols (stride 41)

    u64 taps[6]; mk_taps(taps);
    float num = 0.f, den = 0.f;

    const u64*   base  = g_bufA + (size_t)nk * VOX + (size_t)w * 80;   // + h*6400 + d
    const float* lbase = labels + (size_t)nk * VOX + (size_t)w * 80;   // + h*6400 + d

    #pragma unroll 1
    for (int st = 0; st < 4; st++) {
        int chunk = st & 1;             // d-chunk
        int half  = st >> 1;            // h-half
        int cstart = chunk * 40;        // output d range [cstart, cstart+40)
        int h0     = half * 40;         // output h range [h0, h0+40)
        int dg0    = chunk ? 35 : 0;    // staged d cols: [dg0, dg0+45)

        // stage raw slab: 50 h-rows (h0-5 .. h0+44, zero outside) x 45 d-cols, coalesced
        for (int idx = tid; idx < 50 * 45; idx += 256) {
            int rr = idx / 45, c = idx % 45;
            int hh = h0 - 5 + rr;
            raw[rr * 45 + c] = (hh < 0 || hh >= 80) ? 0ull
                               : __ldg(base + (size_t)hh * 6400 + dg0 + c);
        }
        // stage labels: 40 rows x 40 cols, coalesced along d
        for (int idx = tid; idx < 40 * 40; idx += 256) {
            int lr = idx / 40, dl = idx % 40;
            slab[lr * 41 + dl] = __ldg(lbase + (size_t)(h0 + lr) * 6400 + cstart + dl);
        }
        __syncthreads();

        // spk halo cols (d outside volume): chunk0 -> j in [0,5); chunk1 -> j in [45,50)
        for (int idx = tid; idx < 40 * 5; idx += 256) {
            int lr = idx / 5, p = idx % 5;
            int j = chunk ? 45 + p : p;
            spk[lr * 51 + j] = 0ull;
        }
        // conv along H from raw(smem) -> spk; 225 threads = 45 d-cols x 5 h-segs of 8
        if (tid < 225) {
            int c = tid % 45, hseg = tid / 45;
            int j = chunk ? c : c + 5;           // spk col
            int lr0 = hseg * 8;
            auto load = [&](int i) -> u64 { return raw[(lr0 + i) * 45 + c]; };
            auto emit = [&](int o, u64 a) { spk[(lr0 + o) * 51 + j] = a; };
            slide11<8>(taps, load, emit);
        }
        __syncthreads();

        // conv along D over spk + label reduce; 240 threads = 40 rows x 6 d-segs (7,7,7,7,6,6)
        if (tid < 240) {
            int r = tid % 40, dseg = tid / 40;
            int d0 = (dseg < 4) ? dseg * 7 : 28 + (dseg - 4) * 6;
            auto load = [&](int i) -> u64 { return spk[r * 51 + d0 + i]; };
            auto emit = [&](int o, u64 a) {
                float2 f = unpack2(a);
                float lv = slab[r * 41 + d0 + o];
                den += lv * f.x;
                num += lv * f.y;
            };
            if (dseg < 4) slide11<7>(taps, load, emit);
            else          slide11<6>(taps, load, emit);
        }
        __syncthreads();
    }

    // block reduce num/den
    #pragma unroll
    for (int o = 16; o > 0; o >>= 1) {
        num += __shfl_down_sync(0xffffffffu, num, o);
        den += __shfl_down_sync(0xffffffffu, den, o);
    }
    __shared__ float sn[8], sd[8];
    int wid = tid >> 5, lid = tid & 31;
    if (lid == 0) { sn[wid] = num; sd[wid] = den; }
    __syncthreads();
    if (tid == 0) {
        float tn = 0.f, td = 0.f;
        #pragma unroll
        for (int j = 0; j < 8; j++) { tn += sn[j]; td += sd[j]; }
        g_partC[bx] = make_float2(tn, td);
    }
}

// ---------------- K final: ratio / loss ----------------
__global__ __launch_bounds__(256) void k_final(float* __restrict__ out) {
    int wid = threadIdx.x >> 5, lid = threadIdx.x & 31;   // wid = nk
    __shared__ float sr[8];
    {
        float num = 0.f, den = 0.f;
        for (int j = lid; j < 80; j += 32) {
            float2 p = g_partC[wid * 80 + j];
            num += p.x;
            den += p.y;
        }
        #pragma unroll
        for (int o = 16; o > 0; o >>= 1) {
            num += __shfl_down_sync(0xffffffffu, num, o);
            den += __shfl_down_sync(0xffffffffu, den, o);
        }
        if (lid == 0) sr[wid] = fabsf(num / (den + 1e-6f));
    }
    __syncthreads();
    if (threadIdx.x == 0) {
        float loss = 0.f;
        #pragma unroll
        for (int k = 0; k < 4; k++)
            loss += 0.5f * (sr[k] + sr[4 + k]);
        out[0] = 4.0f - loss;
    }
}

extern "C" void kernel_launch(void* const* d_in, const int* in_sizes, int n_in,
                              void* d_out, int out_size) {
    const float* labels = (const float*)d_in[0];
    const float* inputs = (const float*)d_in[1];
    if (n_in >= 2 && in_sizes[0] < in_sizes[1]) {
        const float* t = labels; labels = inputs; inputs = t;
    }
    float* out = (float*)d_out;

    k_sums <<<dim3(B1, NB), 256>>>(labels, inputs);
    k_means<<<1, 256>>>();
    kA     <<<NK * 80, 256>>>(labels, inputs);
    kB     <<<NK * 80, 256>>>(labels);
    k_final<<<1, 256>>>(out);
}

// round 11
// speedup vs baseline: 1.4159x; 1.4159x over previous
#include <cuda_runtime.h>

#define NB   2
#define NK   8
#define VOX  512000
#define B1   128
#define CHUNK 4000

typedef unsigned long long u64;

// ---------------- packed f32x2 helpers ----------------
__device__ __forceinline__ u64 pack2(float lo, float hi) {
    u64 r; asm("mov.b64 %0,{%1,%2};" : "=l"(r) : "f"(lo), "f"(hi)); return r;
}
__device__ __forceinline__ float2 unpack2(u64 p) {
    float2 f; asm("mov.b64 {%0,%1},%2;" : "=f"(f.x), "=f"(f.y) : "l"(p)); return f;
}
__device__ __forceinline__ void fma2(u64 &a, u64 v, u64 c) {
    asm("fma.rn.f32x2 %0,%1,%2,%0;" : "+l"(a) : "l"(v), "l"(c));
}

// 11-tap unnormalized Gaussian, sigma=4: g[t] = exp(-(t-5)^2/32), symmetric
__device__ __forceinline__ void mk_taps(u64* t) {
    const float g[6] = { 0.45783335f, 0.60653066f, 0.75483960f,
                         0.88249690f, 0.96923321f, 1.00000000f };
    #pragma unroll
    for (int i = 0; i < 6; i++) t[i] = pack2(g[i], g[i]);
}

// Sliding-window 11-tap conv: L outputs, L+10 inputs, 1 load per input,
// ring of 11 packed accumulators. Fully unrolled so %11 folds.
template<int L, typename LoadF, typename EmitF>
__device__ __forceinline__ void slide11(const u64* taps, LoadF&& load, EmitF&& emit) {
    u64 acc[11];
    #pragma unroll
    for (int s = 0; s < 11; s++) acc[s] = 0ull;
    #pragma unroll
    for (int i = 0; i < L + 10; i++) {
        u64 v = load(i);
        #pragma unroll
        for (int j = 0; j <= 10; j++) {
            int o = i - 10 + j;              // tap t = 10-j, coeff g[t]
            if (o >= 0 && o < L) {
                int t = 10 - j;
                int u = (t <= 5) ? t : 10 - t;   // symmetry
                fma2(acc[o % 11], v, taps[u]);
            }
        }
        if (i >= 10) {
            emit(i - 10, acc[(i - 10) % 11]);
            acc[(i - 10) % 11] = 0ull;
        }
    }
}

// ---------------- scratch ----------------
__device__ float  g_part1[NB * B1 * 8];
__device__ float  g_mean[NK];
__device__ u64    g_bufA[NK * VOX];      // after exp + conv-W: (w,pw) packed, [nk][h][w][d]
__device__ float2 g_partC[NK * 80];      // per (nk,w) partial (num,den)

// ---------------- K1: partial sums for class means (float4 streams, R8) ----------------
__global__ __launch_bounds__(256) void k_sums(const float* __restrict__ labels,
                                              const float* __restrict__ inputs) {
    int n = blockIdx.y, b = blockIdx.x;
    int j0 = b * (CHUNK / 4);                 // 1000 float4 per block
    float a[8];
    #pragma unroll
    for (int j = 0; j < 8; j++) a[j] = 0.f;
    const float4* ip4 = (const float4*)(inputs + (size_t)n * VOX);
    for (int j = j0 + threadIdx.x; j < j0 + CHUNK / 4; j += blockDim.x) {
        float4 iv = __ldg(ip4 + j);
        #pragma unroll
        for (int k = 0; k < 4; k++) {
            const float4* lp4 = (const float4*)(labels + (size_t)(n * 4 + k) * VOX);
            float4 lv = __ldg(lp4 + j);
            a[k]     += (lv.x + lv.y) + (lv.z + lv.w);
            a[4 + k] += (iv.x * lv.x + iv.y * lv.y) + (iv.z * lv.z + iv.w * lv.w);
        }
    }
    #pragma unroll
    for (int o = 16; o > 0; o >>= 1)
        #pragma unroll
        for (int j = 0; j < 8; j++)
            a[j] += __shfl_down_sync(0xffffffffu, a[j], o);
    __shared__ float s[8][8];
    int wid = threadIdx.x >> 5, lid = threadIdx.x & 31;
    if (lid == 0)
        #pragma unroll
        for (int j = 0; j < 8; j++) s[wid][j] = a[j];
    __syncthreads();
    if (threadIdx.x < 8) {
        int j = threadIdx.x;
        float acc = 0.f;
        #pragma unroll
        for (int w = 0; w < 8; w++) acc += s[w][j];
        g_part1[(size_t)(n * B1 + b) * 8 + j] = acc;
    }
}

// ---------------- K2: finish means ----------------
__global__ __launch_bounds__(256) void k_means() {
    int wid = threadIdx.x >> 5, lid = threadIdx.x & 31;   // wid = nk
    int n = wid >> 2, k = wid & 3;
    float sp = 0.f, sip = 0.f;
    for (int b = lid; b < B1; b += 32) {
        const float* p = g_part1 + (size_t)(n * B1 + b) * 8;
        sp  += p[k];
        sip += p[4 + k];
    }
    #pragma unroll
    for (int o = 16; o > 0; o >>= 1) {
        sp  += __shfl_down_sync(0xffffffffu, sp, o);
        sip += __shfl_down_sync(0xffffffffu, sip, o);
    }
    if (lid == 0) g_mean[wid] = sip / (sp + 5.12f);   // 1e-5 * 512000
}

// ---------------- KA: exp weights + conv along W (R4-exact) ----------------
// grid = NK*80 (nk,h); threads: 240 active = 80 d-lanes x 3 w-segments
__global__ __launch_bounds__(256) void kA(const float* __restrict__ labels,
                                          const float* __restrict__ inputs) {
    int bx = blockIdx.x;
    int nk = bx / 80, h = bx % 80, n = nk >> 2;
    float m = g_mean[nk];
    int tid = threadIdx.x;
    if (tid >= 240) return;
    int d = tid % 80, seg = tid / 80;
    u64 taps[6]; mk_taps(taps);
    const float* ip = inputs + (size_t)n  * VOX + (size_t)h * 6400 + d;
    const float* lp = labels + (size_t)nk * VOX + (size_t)h * 6400 + d;
    u64*         op = g_bufA + (size_t)nk * VOX + (size_t)h * 6400 + d;
    int w0 = seg * 27;
    auto load = [&](int i) -> u64 {
        int w = w0 - 5 + i;
        if (w < 0 || w >= 80) return 0ull;
        float iv = __ldg(ip + w * 80);
        float lv = __ldg(lp + w * 80);
        float t  = iv - m;
        float q  = t * t; q = q * q;
        float wv = __expf(-q);
        return pack2(wv, lv * wv);
    };
    auto emit = [&](int o, u64 a) { op[(w0 + o) * 80] = a; };
    if (seg < 2) slide11<27>(taps, load, emit);
    else         slide11<26>(taps, load, emit);
}

// ---------------- KB: conv-H + conv-D + fused label reduce (R4-exact) ----------------
// grid = NK*80 (nk,w); d handled in two chunks of 40 outputs (45 staged cols each)
__global__ __launch_bounds__(256) void kB(const float* __restrict__ labels) {
    int bx = blockIdx.x;
    int nk = bx / 80, w = bx % 80;
    int tid = threadIdx.x;
    __shared__ float sw[80 * 51];     // conv-H result, w channel (stride 51, odd)
    __shared__ float spw[80 * 51];    // conv-H result, pw channel
    __shared__ float slab[80 * 41];   // labels (stride 41, odd)

    u64 taps[6]; mk_taps(taps);
    float num = 0.f, den = 0.f;

    const u64*   base  = g_bufA + (size_t)nk * VOX + (size_t)w * 80;
    const float* lbase = labels + (size_t)nk * VOX + (size_t)w * 80;

    for (int chunk = 0; chunk < 2; chunk++) {
        int cstart = chunk * 40;       // output d range [cstart, cstart+40)
        // zero pad cols: chunk0 -> j in [0,5) (d<0); chunk1 -> j in [45,50) (d>=80)
        for (int idx = tid; idx < 80 * 5; idx += 256) {
            int r = idx / 5, p = idx % 5;
            int j = (chunk == 0) ? p : 45 + p;
            sw[r * 51 + j]  = 0.f;
            spw[r * 51 + j] = 0.f;
        }
        // stage1: conv along H into smem; 225 threads = 45 d-cols x 5 h-segments of 16
        if (tid < 225) {
            int jv = tid % 45, hseg = tid / 45;
            int j  = (chunk == 0) ? jv + 5 : jv;      // smem col
            int dg = (chunk == 0) ? jv     : 35 + jv; // global d
            int h0 = hseg * 16;
            const u64* cp = base + dg;
            auto load = [&](int i) -> u64 {
                int hh = h0 - 5 + i;
                return (hh < 0 || hh >= 80) ? 0ull : __ldg(cp + (size_t)hh * 6400);
            };
            auto emit = [&](int o, u64 a) {
                float2 f = unpack2(a);
                int r = h0 + o;
                sw[r * 51 + j]  = f.x;
                spw[r * 51 + j] = f.y;
            };
            slide11<16>(taps, load, emit);
        }
        // stage labels (coalesced)
        for (int idx = tid; idx < 80 * 40; idx += 256) {
            int r = idx / 40, dl = idx % 40;
            slab[r * 41 + dl] = __ldg(lbase + (size_t)r * 6400 + cstart + dl);
        }
        __syncthreads();
        // stage2: conv along D sliding over smem + label reduce
        // 240 threads = 80 h-rows x 3 d-segments (14,14,12)
        if (tid < 240) {
            int r = tid % 80, dseg = tid / 80;
            int d0 = dseg * 14;
            auto load = [&](int i) -> u64 {
                int j = d0 + i;
                return pack2(sw[r * 51 + j], spw[r * 51 + j]);
            };
            auto emit = [&](int o, u64 a) {
                float2 f = unpack2(a);
                float lv = slab[r * 41 + d0 + o];
                den += lv * f.x;
                num += lv * f.y;
            };
            if (dseg < 2) slide11<14>(taps, load, emit);
            else          slide11<12>(taps, load, emit);
        }
        __syncthreads();
    }

    // block reduce num/den
    #pragma unroll
    for (int o = 16; o > 0; o >>= 1) {
        num += __shfl_down_sync(0xffffffffu, num, o);
        den += __shfl_down_sync(0xffffffffu, den, o);
    }
    __shared__ float sn[8], sd[8];
    int wid = tid >> 5, lid = tid & 31;
    if (lid == 0) { sn[wid] = num; sd[wid] = den; }
    __syncthreads();
    if (tid == 0) {
        float tn = 0.f, td = 0.f;
        #pragma unroll
        for (int j = 0; j < 8; j++) { tn += sn[j]; td += sd[j]; }
        g_partC[bx] = make_float2(tn, td);
    }
}

// ---------------- K final: ratio / loss ----------------
__global__ __launch_bounds__(256) void k_final(float* __restrict__ out) {
    int wid = threadIdx.x >> 5, lid = threadIdx.x & 31;   // wid = nk
    __shared__ float sr[8];
    {
        float num = 0.f, den = 0.f;
        for (int j = lid; j < 80; j += 32) {
            float2 p = g_partC[wid * 80 + j];
            num += p.x;
            den += p.y;
        }
        #pragma unroll
        for (int o = 16; o > 0; o >>= 1) {
            num += __shfl_down_sync(0xffffffffu, num, o);
            den += __shfl_down_sync(0xffffffffu, den, o);
        }
        if (lid == 0) sr[wid] = fabsf(num / (den + 1e-6f));
    }
    __syncthreads();
    if (threadIdx.x == 0) {
        float loss = 0.f;
        #pragma unroll
        for (int k = 0; k < 4; k++)
            loss += 0.5f * (sr[k] + sr[4 + k]);
        out[0] = 4.0f - loss;
    }
}

extern "C" void kernel_launch(void* const* d_in, const int* in_sizes, int n_in,
                              void* d_out, int out_size) {
    const float* labels = (const float*)d_in[0];
    const float* inputs = (const float*)d_in[1];
    if (n_in >= 2 && in_sizes[0] < in_sizes[1]) {
        const float* t = labels; labels = inputs; inputs = t;
    }
    float* out = (float*)d_out;

    k_sums <<<dim3(B1, NB), 256>>>(labels, inputs);
    k_means<<<1, 256>>>();
    kA     <<<NK * 80, 256>>>(labels, inputs);
    kB     <<<NK * 80, 256>>>(labels);
    k_final<<<1, 256>>>(out);
}